// round 8
// baseline (speedup 1.0000x reference)
#include <cuda_runtime.h>

#define TT   1024
#define BB   16
#define HH   512
#define G4H  2048
#define NBLK 128
#define FTHR 384

typedef unsigned long long ull;

// ------------- device-global scratch (no runtime allocation allowed) -------------
__device__ float g_gx[(size_t)BB * TT * G4H];        // 134 MB: gx0[b][t][gatecol]
__device__ __align__(16) ull g_h0buf[2][16 * 256];   // h0 exchange, [b][kp] k-pairs
__device__ __align__(16) ull g_h1buf[2][16 * 256];   // h1 exchange
__device__ unsigned g_bar_count = 0;
__device__ unsigned g_bar_epoch = 0;

// ------------- packed f32x2 ops (only reachable via PTX) -------------
__device__ __forceinline__ void fma2(ull& d, ull a, ull b)
{
    asm("fma.rn.f32x2 %0, %1, %2, %0;" : "+l"(d) : "l"(a), "l"(b));
}
__device__ __forceinline__ ull pack2(float a, float b)
{
    ull r; asm("mov.b64 %0, {%1, %2};" : "=l"(r) : "f"(a), "f"(b)); return r;
}
__device__ __forceinline__ float2 unpack2(ull v)
{
    float2 r; asm("mov.b64 {%0, %1}, %2;" : "=f"(r.x), "=f"(r.y) : "l"(v)); return r;
}
__device__ __forceinline__ void ldcg_v2u64(ull& a, ull& b, const ull* p)
{
    asm volatile("ld.global.cg.v2.u64 {%0, %1}, [%2];" : "=l"(a), "=l"(b) : "l"(p));
}

// fast activations (MUFU-based, err ~1e-6)
__device__ __forceinline__ float sigm_f(float x) { return 1.f / (1.f + __expf(-x)); }
__device__ __forceinline__ float tanh_f(float x)
{
    float e = __expf(2.f * x);
    return 1.f - 2.f / (e + 1.f);
}

// =====================================================================
// GEMM (layer-0 input projection): g_gx[m][n] = sum_k X[m][k]*W[n][k] + bias[n]
// M=16384, N=2048, K=512. BM=BN=128, BK=16, 256 thr, 8x8 tiles, f32x2.
// =====================================================================
__global__ void __launch_bounds__(256, 2) gemm_xw(const float* __restrict__ X,
                                                  const float* __restrict__ W,
                                                  const float* __restrict__ bias)
{
    __shared__ float2 As[16][130];
    __shared__ float  Bs[16][132];

    const int m0  = blockIdx.y * 128;
    const int n0  = blockIdx.x * 128;
    const int tid = threadIdx.x;
    const int tm  = tid >> 4;
    const int tn  = tid & 15;
    const int lr  = tid >> 2;
    const int lk  = (tid & 3) * 4;

    ull acc[8][4];
#pragma unroll
    for (int i = 0; i < 8; i++)
#pragma unroll
        for (int j = 0; j < 4; j++) acc[i][j] = 0ULL;

    for (int k0 = 0; k0 < 512; k0 += 16) {
        float4 av0 = *(const float4*)&X[(size_t)(m0 + lr)      * 512 + k0 + lk];
        float4 av1 = *(const float4*)&X[(size_t)(m0 + lr + 64) * 512 + k0 + lk];
        float4 bv0 = *(const float4*)&W[(size_t)(n0 + lr)      * 512 + k0 + lk];
        float4 bv1 = *(const float4*)&W[(size_t)(n0 + lr + 64) * 512 + k0 + lk];

        __syncthreads();
        As[lk + 0][lr]      = make_float2(av0.x, av0.x);
        As[lk + 1][lr]      = make_float2(av0.y, av0.y);
        As[lk + 2][lr]      = make_float2(av0.z, av0.z);
        As[lk + 3][lr]      = make_float2(av0.w, av0.w);
        As[lk + 0][lr + 64] = make_float2(av1.x, av1.x);
        As[lk + 1][lr + 64] = make_float2(av1.y, av1.y);
        As[lk + 2][lr + 64] = make_float2(av1.z, av1.z);
        As[lk + 3][lr + 64] = make_float2(av1.w, av1.w);
        Bs[lk + 0][lr]      = bv0.x;
        Bs[lk + 1][lr]      = bv0.y;
        Bs[lk + 2][lr]      = bv0.z;
        Bs[lk + 3][lr]      = bv0.w;
        Bs[lk + 0][lr + 64] = bv1.x;
        Bs[lk + 1][lr + 64] = bv1.y;
        Bs[lk + 2][lr + 64] = bv1.z;
        Bs[lk + 3][lr + 64] = bv1.w;
        __syncthreads();

#pragma unroll
        for (int k = 0; k < 16; k++) {
            ull a[8], b[4];
            ulonglong2 q;
            q = *(const ulonglong2*)&As[k][tm * 8 + 0]; a[0] = q.x; a[1] = q.y;
            q = *(const ulonglong2*)&As[k][tm * 8 + 2]; a[2] = q.x; a[3] = q.y;
            q = *(const ulonglong2*)&As[k][tm * 8 + 4]; a[4] = q.x; a[5] = q.y;
            q = *(const ulonglong2*)&As[k][tm * 8 + 6]; a[6] = q.x; a[7] = q.y;
            q = *(const ulonglong2*)&Bs[k][tn * 8 + 0]; b[0] = q.x; b[1] = q.y;
            q = *(const ulonglong2*)&Bs[k][tn * 8 + 4]; b[2] = q.x; b[3] = q.y;
#pragma unroll
            for (int i = 0; i < 8; i++)
#pragma unroll
                for (int j = 0; j < 4; j++)
                    fma2(acc[i][j], a[i], b[j]);
        }
    }

    float bl[8];
#pragma unroll
    for (int j = 0; j < 8; j++) bl[j] = bias[n0 + tn * 8 + j];

#pragma unroll
    for (int i = 0; i < 8; i++) {
        int row = m0 + tm * 8 + i;
        float2 v0 = unpack2(acc[i][0]), v1 = unpack2(acc[i][1]);
        float2 v2 = unpack2(acc[i][2]), v3 = unpack2(acc[i][3]);
        float4 o0 = make_float4(v0.x + bl[0], v0.y + bl[1], v1.x + bl[2], v1.y + bl[3]);
        float4 o1 = make_float4(v2.x + bl[4], v2.y + bl[5], v3.x + bl[6], v3.y + bl[7]);
        *(float4*)&g_gx[(size_t)row * G4H + n0 + tn * 8]     = o0;
        *(float4*)&g_gx[(size_t)row * G4H + n0 + tn * 8 + 4] = o1;
    }
}

// =====================================================================
// Grid barrier for 128 co-resident blocks (1 wave).
// =====================================================================
__device__ __forceinline__ void grid_barrier(unsigned target)
{
    __threadfence();
    __syncthreads();
    if (threadIdx.x == 0) {
        unsigned t = atomicAdd(&g_bar_count, 1);
        if (t == NBLK - 1) {
            atomicExch(&g_bar_count, 0);
            __threadfence();
            atomicAdd(&g_bar_epoch, 1);
        } else {
            while ((int)(*(volatile unsigned*)&g_bar_epoch - target) < 0) { }
        }
    }
    __syncthreads();
}

// =====================================================================
// Fused systolic 2-layer LSTM. 128 blocks x 384 threads, 1025 super-steps.
// Super-step s computes h0(s) [layer 0] and h1(s-1) [layer 1].
// Block owns 4 hidden units j0..j0+3 per layer -> 16 gate cols per matrix.
// 3 roles x 128 threads: A = w_hh_0 @ h0(s-1), B = w_ih_1 @ h0(s-1),
// C = w_hh_1 @ h1(s-2). k-pair packing: w-pairs (w_k, w_{k+1}) in f32x2,
// per-batch accumulators, halves folded at reduce.
// Thread (col = rtid>>3, ksub = rtid&7): 64 k values = 32 ull w regs.
// h tiles staged as [b][kp] pairs: lanes (col&3)*8+ksub -> 128B contiguous
// per warp LDS with 4-way broadcast, conflict-free.
// =====================================================================
__global__ void __launch_bounds__(FTHR, 1) lstm_fused(
    const float* __restrict__ w_hh0, const float* __restrict__ b_hh0,
    const float* __restrict__ w_ih1, const float* __restrict__ w_hh1,
    const float* __restrict__ b_ih1, const float* __restrict__ b_hh1,
    const float* __restrict__ h0in,  const float* __restrict__ c0in,
    float* __restrict__ out)
{
    extern __shared__ __align__(16) char smraw[];
    ull*   tile0 = (ull*)(smraw);                 // h0(s-1) pairs [b][kp], 32 KB
    ull*   tile1 = (ull*)(smraw + 32768);         // h1(s-2) pairs, 32 KB
    float* gredA = (float*)(smraw + 65536);       // [col][b] 1 KB
    float* gredB = (float*)(smraw + 66560);
    float* gredC = (float*)(smraw + 67584);
    float* gact0 = (float*)(smraw + 68608);       // [col][b] 1 KB
    float* gact1 = (float*)(smraw + 69632);
    float* c0s   = (float*)(smraw + 70656);       // [j][b] 256 B
    float* c1s   = (float*)(smraw + 70912);

    const int tid  = threadIdx.x;
    const int blk  = blockIdx.x;
    const int j0   = blk * 4;
    const int role = tid >> 7;           // 0=A,1=B,2=C
    const int rtid = tid & 127;
    const int col  = rtid >> 3;          // 0..15
    const int ksub = rtid & 7;           // 0..7
    const int gcol = (col >> 2) * 512 + j0 + (col & 3);

    // ---- weights for this role into registers (k-pair packed) ----
    const float* wsrc = (role == 0) ? w_hh0 : (role == 1) ? w_ih1 : w_hh1;
    ull wreg[32];
#pragma unroll
    for (int i = 0; i < 16; i++) {
        float4 w4 = *(const float4*)&wsrc[(size_t)gcol * 512 + i * 32 + ksub * 4];
        wreg[2 * i]     = pack2(w4.x, w4.y);
        wreg[2 * i + 1] = pack2(w4.z, w4.w);
    }

    // ---- per-thread reducer constants ----
    // gates0 reducers: tid 0..255 -> (c0l = tid>>4, b0l = tid&15)
    const int c0l = tid >> 4, b0l = tid & 15;
    const int gc0 = (c0l >> 2) * 512 + j0 + (c0l & 3);
    float bh0 = 0.f;
    if (tid < 256) bh0 = b_hh0[gc0];
    // gates1 reducers: tid 128..383 -> (c1l, b1l)
    const int rt1 = (tid - 128) & 255;
    const int c1l = rt1 >> 4, b1l = rt1 & 15;
    const int gc1 = (c1l >> 2) * 512 + j0 + (c1l & 3);
    float bs1 = 0.f;
    if (tid >= 128) bs1 = b_ih1[gc1] + b_hh1[gc1];

    // ---- init cell states + initial h exchange ----
    if (tid < 64) {
        int j = tid >> 4, b = tid & 15;
        c0s[j * 16 + b] = c0in[b * 512 + j0 + j];
    } else if (tid < 128) {
        int j = (tid - 64) >> 4, b = tid & 15;
        c1s[j * 16 + b] = c0in[BB * HH + b * 512 + j0 + j];
    }
    if (tid < 32) {
        int jp = tid >> 4, b = tid & 15;
        g_h0buf[1][b * 256 + (j0 >> 1) + jp] =
            pack2(h0in[b * 512 + j0 + 2 * jp], h0in[b * 512 + j0 + 2 * jp + 1]);
    } else if (tid < 64) {
        int jp = (tid - 32) >> 4, b = tid & 15;
        g_h1buf[1][b * 256 + (j0 >> 1) + jp] =
            pack2(h0in[BB * HH + b * 512 + j0 + 2 * jp],
                  h0in[BB * HH + b * 512 + j0 + 2 * jp + 1]);
    }

    unsigned base = 0;
    if (tid == 0) base = *(volatile unsigned*)&g_bar_epoch;
    grid_barrier(base + 1);

    for (int s = 0; s <= TT; s++) {
        const ull* src0 = g_h0buf[(s + 1) & 1];   // h0(s-1)
        ull*       dst0 = g_h0buf[s & 1];         // h0(s)
        const ull* src1 = g_h1buf[s & 1];         // h1(s-2)
        ull*       dst1 = g_h1buf[(s + 1) & 1];   // h1(s-1)

        // prefetch gx0 for reducers (DRAM, consumed ~3000 cyc later)
        float gx0v = 0.f;
        if (tid < 256 && s < TT)
            gx0v = g_gx[((size_t)b0l * TT + s) * G4H + gc0];

        // ---- stage h tiles (L1 bypass) ----
        if (role < 2) {
            ull ta[8], tb[8];
#pragma unroll
            for (int r = 0; r < 8; r++)
                ldcg_v2u64(ta[r], tb[r], src0 + 2 * (tid + r * 256));
#pragma unroll
            for (int r = 0; r < 8; r++) {
                tile0[2 * (tid + r * 256)]     = ta[r];
                tile0[2 * (tid + r * 256) + 1] = tb[r];
            }
        } else {
            ull ta[8], tb[8];
#pragma unroll
            for (int r = 0; r < 8; r++)
                ldcg_v2u64(ta[r], tb[r], src1 + 2 * (rtid + r * 128));
#pragma unroll
            for (int r = 0; r < 8; r++) {
                tile1[2 * (rtid + r * 128)]     = ta[r];
                tile1[2 * (rtid + r * 128) + 1] = tb[r];
            }
#pragma unroll
            for (int r = 8; r < 16; r++)
                ldcg_v2u64(ta[r - 8], tb[r - 8], src1 + 2 * (rtid + r * 128));
#pragma unroll
            for (int r = 8; r < 16; r++) {
                tile1[2 * (rtid + r * 128)]     = ta[r - 8];
                tile1[2 * (rtid + r * 128) + 1] = tb[r - 8];
            }
        }
        __syncthreads();

        // ---- MMA: 16 per-batch accumulators, k-pair packed ----
        const ull* tile = (role == 2) ? tile1 : tile0;
        ull acc[16];
#pragma unroll
        for (int b = 0; b < 16; b++) acc[b] = 0ULL;
#pragma unroll
        for (int i = 0; i < 16; i++) {
            const int off = i * 16 + ksub * 2;
#pragma unroll
            for (int b = 0; b < 16; b++) {
                ulonglong2 q = *(const ulonglong2*)&tile[b * 256 + off];
                fma2(acc[b], wreg[2 * i],     q.x);
                fma2(acc[b], wreg[2 * i + 1], q.y);
            }
        }

        // ---- fold halves + in-warp reduce over ksub (xor 1,2,4) ----
        float sv[16];
#pragma unroll
        for (int b = 0; b < 16; b++) {
            float2 p = unpack2(acc[b]);
            sv[b] = p.x + p.y;
        }
#pragma unroll
        for (int m = 1; m <= 4; m <<= 1)
#pragma unroll
            for (int b = 0; b < 16; b++)
                sv[b] += __shfl_xor_sync(0xffffffffu, sv[b], m);
        if (ksub == 0) {
            float* gr = (role == 0) ? gredA : (role == 1) ? gredB : gredC;
#pragma unroll
            for (int m = 0; m < 16; m += 4)
                *(float4*)&gr[col * 16 + m] =
                    make_float4(sv[m], sv[m + 1], sv[m + 2], sv[m + 3]);
        }
        __syncthreads();

        // ---- gates ----
        if (tid < 256 && s < TT) {
            float v = gredA[tid] + gx0v + bh0;
            gact0[tid] = ((c0l >> 2) == 2) ? tanh_f(v) : sigm_f(v);
        }
        if (tid >= 128 && s >= 1) {
            float v = gredB[rt1] + gredC[rt1] + bs1;
            gact1[rt1] = ((c1l >> 2) == 2) ? tanh_f(v) : sigm_f(v);
        }
        __syncthreads();

        // ---- cell/hidden updates (writers handle unit pairs) ----
        if (tid < 32 && s < TT) {
            int jp = tid >> 4, b = tid & 15;
            float hx[2];
#pragma unroll
            for (int u = 0; u < 2; u++) {
                int j = 2 * jp + u;
                float iv = gact0[(0  + j) * 16 + b];
                float fv = gact0[(4  + j) * 16 + b];
                float gv = gact0[(8  + j) * 16 + b];
                float ov = gact0[(12 + j) * 16 + b];
                float c  = fv * c0s[j * 16 + b] + iv * gv;
                c0s[j * 16 + b] = c;
                hx[u] = ov * tanh_f(c);
                if (s == TT - 1) out[b * HH + j0 + j] = hx[u];
            }
            dst0[b * 256 + (j0 >> 1) + jp] = pack2(hx[0], hx[1]);
        } else if (tid >= 32 && tid < 64 && s >= 1) {
            int jp = (tid - 32) >> 4, b = tid & 15;
            float hx[2];
#pragma unroll
            for (int u = 0; u < 2; u++) {
                int j = 2 * jp + u;
                float iv = gact1[(0  + j) * 16 + b];
                float fv = gact1[(4  + j) * 16 + b];
                float gv = gact1[(8  + j) * 16 + b];
                float ov = gact1[(12 + j) * 16 + b];
                float c  = fv * c1s[j * 16 + b] + iv * gv;
                c1s[j * 16 + b] = c;
                hx[u] = ov * tanh_f(c);
                if (s == TT) out[BB * HH + b * HH + j0 + j] = hx[u];
            }
            dst1[b * 256 + (j0 >> 1) + jp] = pack2(hx[0], hx[1]);
        }
        grid_barrier(base + 2 + s);
    }
}

// =====================================================================
extern "C" void kernel_launch(void* const* d_in, const int* in_sizes, int n_in,
                              void* d_out, int out_size)
{
    const float* x      = (const float*)d_in[0];
    const float* h0     = (const float*)d_in[1];   // (2, B, H)
    const float* c0     = (const float*)d_in[2];   // (2, B, H)
    const float* w_ih_0 = (const float*)d_in[3];
    const float* w_hh_0 = (const float*)d_in[4];
    const float* b_ih_0 = (const float*)d_in[5];
    const float* b_hh_0 = (const float*)d_in[6];
    const float* w_ih_1 = (const float*)d_in[7];
    const float* w_hh_1 = (const float*)d_in[8];
    const float* b_ih_1 = (const float*)d_in[9];
    const float* b_hh_1 = (const float*)d_in[10];
    float* out = (float*)d_out;                    // (2, B, H)

    static int smem_set = 0;
    const int SMEMB = 72 * 1024;
    if (!smem_set) {
        cudaFuncSetAttribute(lstm_fused,
                             cudaFuncAttributeMaxDynamicSharedMemorySize, SMEMB);
        smem_set = 1;
    }

    dim3 ggrid(16, 128);   // N/128, M/128
    gemm_xw<<<ggrid, 256>>>(x, w_ih_0, b_ih_0);
    lstm_fused<<<NBLK, FTHR, SMEMB>>>(w_hh_0, b_hh_0,
                                      w_ih_1, w_hh_1, b_ih_1, b_hh_1,
                                      h0, c0, out);
}

// round 9
// speedup vs baseline: 1.1560x; 1.1560x over previous
#include <cuda_runtime.h>

#define TT   1024
#define BB   16
#define HH   512
#define G4H  2048
#define NBLK 256
#define NTHR 256

typedef unsigned long long ull;

// ------------- device-global scratch (no runtime allocation allowed) -------------
__device__ float g_gx[(size_t)BB * TT * G4H];        // 134 MB: gx0[b][t][gatecol]
__device__ __align__(16) ull g_h0buf[2][16 * 256];   // h0 exchange, [b][kp], kp-pair packed
__device__ __align__(16) ull g_h1buf[2][16 * 256];   // h1 exchange
__device__ unsigned g_bar_count = 0;
__device__ unsigned g_bar_epoch = 0;

// ------------- packed f32x2 ops (only reachable via PTX) -------------
__device__ __forceinline__ void fma2(ull& d, ull a, ull b)
{
    asm("fma.rn.f32x2 %0, %1, %2, %0;" : "+l"(d) : "l"(a), "l"(b));
}
__device__ __forceinline__ ull pack2(float a, float b)
{
    ull r; asm("mov.b64 %0, {%1, %2};" : "=l"(r) : "f"(a), "f"(b)); return r;
}
__device__ __forceinline__ float2 unpack2(ull v)
{
    float2 r; asm("mov.b64 {%0, %1}, %2;" : "=f"(r.x), "=f"(r.y) : "l"(v)); return r;
}
__device__ __forceinline__ void ldcg_v2u64(ull& a, ull& b, const ull* p)
{
    asm volatile("ld.global.cg.v2.u64 {%0, %1}, [%2];" : "=l"(a), "=l"(b) : "l"(p));
}

// fast activations (MUFU-based, err ~1e-6)
__device__ __forceinline__ float sigm_f(float x) { return 1.f / (1.f + __expf(-x)); }
__device__ __forceinline__ float tanh_f(float x)
{
    float e = __expf(2.f * x);
    return 1.f - 2.f / (e + 1.f);
}

// =====================================================================
// GEMM (layer-0 input projection): g_gx[m][n] = sum_k X[m][k]*W[n][k] + bias[n]
// M=16384, N=2048, K=512. BM=BN=128, BK=16, 256 thr, 8x8 tiles, f32x2.
// =====================================================================
__global__ void __launch_bounds__(256, 2) gemm_xw(const float* __restrict__ X,
                                                  const float* __restrict__ W,
                                                  const float* __restrict__ bias)
{
    __shared__ float2 As[16][130];
    __shared__ float  Bs[16][132];

    const int m0  = blockIdx.y * 128;
    const int n0  = blockIdx.x * 128;
    const int tid = threadIdx.x;
    const int tm  = tid >> 4;
    const int tn  = tid & 15;
    const int lr  = tid >> 2;
    const int lk  = (tid & 3) * 4;

    ull acc[8][4];
#pragma unroll
    for (int i = 0; i < 8; i++)
#pragma unroll
        for (int j = 0; j < 4; j++) acc[i][j] = 0ULL;

    for (int k0 = 0; k0 < 512; k0 += 16) {
        float4 av0 = *(const float4*)&X[(size_t)(m0 + lr)      * 512 + k0 + lk];
        float4 av1 = *(const float4*)&X[(size_t)(m0 + lr + 64) * 512 + k0 + lk];
        float4 bv0 = *(const float4*)&W[(size_t)(n0 + lr)      * 512 + k0 + lk];
        float4 bv1 = *(const float4*)&W[(size_t)(n0 + lr + 64) * 512 + k0 + lk];

        __syncthreads();
        As[lk + 0][lr]      = make_float2(av0.x, av0.x);
        As[lk + 1][lr]      = make_float2(av0.y, av0.y);
        As[lk + 2][lr]      = make_float2(av0.z, av0.z);
        As[lk + 3][lr]      = make_float2(av0.w, av0.w);
        As[lk + 0][lr + 64] = make_float2(av1.x, av1.x);
        As[lk + 1][lr + 64] = make_float2(av1.y, av1.y);
        As[lk + 2][lr + 64] = make_float2(av1.z, av1.z);
        As[lk + 3][lr + 64] = make_float2(av1.w, av1.w);
        Bs[lk + 0][lr]      = bv0.x;
        Bs[lk + 1][lr]      = bv0.y;
        Bs[lk + 2][lr]      = bv0.z;
        Bs[lk + 3][lr]      = bv0.w;
        Bs[lk + 0][lr + 64] = bv1.x;
        Bs[lk + 1][lr + 64] = bv1.y;
        Bs[lk + 2][lr + 64] = bv1.z;
        Bs[lk + 3][lr + 64] = bv1.w;
        __syncthreads();

#pragma unroll
        for (int k = 0; k < 16; k++) {
            ull a[8], b[4];
            ulonglong2 q;
            q = *(const ulonglong2*)&As[k][tm * 8 + 0]; a[0] = q.x; a[1] = q.y;
            q = *(const ulonglong2*)&As[k][tm * 8 + 2]; a[2] = q.x; a[3] = q.y;
            q = *(const ulonglong2*)&As[k][tm * 8 + 4]; a[4] = q.x; a[5] = q.y;
            q = *(const ulonglong2*)&As[k][tm * 8 + 6]; a[6] = q.x; a[7] = q.y;
            q = *(const ulonglong2*)&Bs[k][tn * 8 + 0]; b[0] = q.x; b[1] = q.y;
            q = *(const ulonglong2*)&Bs[k][tn * 8 + 4]; b[2] = q.x; b[3] = q.y;
#pragma unroll
            for (int i = 0; i < 8; i++)
#pragma unroll
                for (int j = 0; j < 4; j++)
                    fma2(acc[i][j], a[i], b[j]);
        }
    }

    float bl[8];
#pragma unroll
    for (int j = 0; j < 8; j++) bl[j] = bias[n0 + tn * 8 + j];

#pragma unroll
    for (int i = 0; i < 8; i++) {
        int row = m0 + tm * 8 + i;
        float2 v0 = unpack2(acc[i][0]), v1 = unpack2(acc[i][1]);
        float2 v2 = unpack2(acc[i][2]), v3 = unpack2(acc[i][3]);
        float4 o0 = make_float4(v0.x + bl[0], v0.y + bl[1], v1.x + bl[2], v1.y + bl[3]);
        float4 o1 = make_float4(v2.x + bl[4], v2.y + bl[5], v3.x + bl[6], v3.y + bl[7]);
        *(float4*)&g_gx[(size_t)row * G4H + n0 + tn * 8]     = o0;
        *(float4*)&g_gx[(size_t)row * G4H + n0 + tn * 8 + 4] = o1;
    }
}

// =====================================================================
// Grid barrier for 256 co-resident blocks (2 per SM).
// base-epoch snapshot is race-free: epoch only advances after ALL blocks
// arrive, so any pre-arrival read sees the stable previous value.
// =====================================================================
__device__ __forceinline__ void grid_barrier(unsigned target)
{
    __threadfence();
    __syncthreads();
    if (threadIdx.x == 0) {
        unsigned t = atomicAdd(&g_bar_count, 1);
        if (t == NBLK - 1) {
            atomicExch(&g_bar_count, 0);
            __threadfence();
            atomicAdd(&g_bar_epoch, 1);
        } else {
            while ((int)(*(volatile unsigned*)&g_bar_epoch - target) < 0) { }
        }
    }
    __syncthreads();
}

// =====================================================================
// Dual-layer persistent LSTM. 256 blocks x 256 threads, 2 blocks/SM.
// Blocks 0-127: layer 0 (h0(s) at super-step s, s=0..TT-1).
// Blocks 128-255: layer 1 (h1(s-1) at super-step s, s=1..TT), consuming
//   h0(s-1) [w_ih1] and h1(s-2) [w_hh1] with ONE shared accumulator set.
// Exchange format: [b][kp] where value = (h[b][2kp], h[b][2kp+1]).
// MMA thread (l = tid&15, ksub = tid>>4): k-pairs {i*32+ksub*2, +1},
// i=0..7 -> 16 ull k-pair-packed w regs per matrix, 16 per-batch accs.
// Per-warp h loads: 2 adjacent 16B chunks, 16-way broadcast, conflict-free.
// =====================================================================
__global__ void __launch_bounds__(NTHR, 2) lstm_dual(
    const float* __restrict__ w_hh0, const float* __restrict__ b_hh0,
    const float* __restrict__ w_ih1, const float* __restrict__ w_hh1,
    const float* __restrict__ b_ih1, const float* __restrict__ b_hh1,
    const float* __restrict__ h0in,  const float* __restrict__ c0in,
    float* __restrict__ out)
{
    extern __shared__ __align__(16) char smraw[];
    ull*   tile0 = (ull*)(smraw);            // staged h0(s-1) [b][kp], 32 KB
    ull*   tile1 = (ull*)(smraw + 32768);    // staged h1(s-2), 32 KB (L1 blocks)
    float* red   = (float*)(smraw + 65536);  // [w][b][l] partials, 8 KB
    float* gact  = (float*)(smraw + 73728);  // [col][b], 1 KB
    float* cs    = (float*)(smraw + 74752);  // [j][b], 256 B

    const int tid  = threadIdx.x;
    const int blk  = blockIdx.x;
    const bool isL1 = blk >= 128;
    const int j0   = (blk & 127) * 4;
    const int l    = tid & 15;           // MMA col
    const int ksub = tid >> 4;           // 0..15
    const int wid  = tid >> 5;
    const int gcol = (l >> 2) * 512 + j0 + (l & 3);

    // ---- weights into registers, k-pair packed: (w_2kp, w_2kp+1) ----
    ull wA[16], wB[16];
    {
        const float* srcA = isL1 ? w_ih1 : w_hh0;
#pragma unroll
        for (int i = 0; i < 8; i++) {
            float4 w4 = *(const float4*)&srcA[(size_t)gcol * 512 + i * 64 + ksub * 4];
            wA[2 * i]     = pack2(w4.x, w4.y);
            wA[2 * i + 1] = pack2(w4.z, w4.w);
        }
        if (isL1) {
#pragma unroll
            for (int i = 0; i < 8; i++) {
                float4 w4 = *(const float4*)&w_hh1[(size_t)gcol * 512 + i * 64 + ksub * 4];
                wB[2 * i]     = pack2(w4.x, w4.y);
                wB[2 * i + 1] = pack2(w4.z, w4.w);
            }
        } else {
#pragma unroll
            for (int i = 0; i < 16; i++) wB[i] = 0ULL;
        }
    }

    // ---- gates-role constants: col = tid>>4, b = tid&15 ----
    const int gcolG = tid >> 4;
    const int gbG   = tid & 15;
    const int ggc   = (gcolG >> 2) * 512 + j0 + (gcolG & 3);
    const float bh  = isL1 ? (b_ih1[ggc] + b_hh1[ggc]) : b_hh0[ggc];

    // ---- init cell state + initial h exchange (each block its own slice) ----
    const float* hinit = h0in + (isL1 ? BB * HH : 0);
    const float* cinit = c0in + (isL1 ? BB * HH : 0);
    if (tid < 64) {
        int j = tid >> 4, b = tid & 15;
        cs[j * 16 + b] = cinit[b * 512 + j0 + j];
    }
    if (tid < 32) {
        int jp = tid >> 4, b = tid & 15;
        ull v = pack2(hinit[b * 512 + j0 + 2 * jp], hinit[b * 512 + j0 + 2 * jp + 1]);
        if (isL1) g_h1buf[1][b * 256 + (j0 >> 1) + jp] = v;
        else      g_h0buf[1][b * 256 + (j0 >> 1) + jp] = v;
    }

    unsigned base = 0;
    if (tid == 0) base = *(volatile unsigned*)&g_bar_epoch;
    grid_barrier(base + 1);

    for (int s = 0; s <= TT; s++) {
        const bool active = isL1 ? (s >= 1) : (s < TT);
        if (active) {
            const ull* src0 = g_h0buf[(s + 1) & 1];   // h0(s-1)
            ull*       dst0 = g_h0buf[s & 1];         // h0(s)
            const ull* src1 = g_h1buf[s & 1];         // h1(s-2)
            ull*       dst1 = g_h1buf[(s + 1) & 1];   // h1(s-1)

            // gx prefetch (layer 0 only; consumed ~2000 cyc later)
            float gxv = 0.f;
            if (!isL1)
                gxv = g_gx[((size_t)gbG * TT + s) * G4H + ggc];

            // ---- stage h tiles: L1 bypass, rounds of 4 to cap live regs ----
#pragma unroll
            for (int r = 0; r < 2; r++) {
                ull ta[4], tb[4];
#pragma unroll
                for (int q = 0; q < 4; q++)
                    ldcg_v2u64(ta[q], tb[q], src0 + 2 * (tid + (r * 4 + q) * 256));
#pragma unroll
                for (int q = 0; q < 4; q++) {
                    tile0[2 * (tid + (r * 4 + q) * 256)]     = ta[q];
                    tile0[2 * (tid + (r * 4 + q) * 256) + 1] = tb[q];
                }
            }
            if (isL1) {
#pragma unroll
                for (int r = 0; r < 2; r++) {
                    ull ta[4], tb[4];
#pragma unroll
                    for (int q = 0; q < 4; q++)
                        ldcg_v2u64(ta[q], tb[q], src1 + 2 * (tid + (r * 4 + q) * 256));
#pragma unroll
                    for (int q = 0; q < 4; q++) {
                        tile1[2 * (tid + (r * 4 + q) * 256)]     = ta[q];
                        tile1[2 * (tid + (r * 4 + q) * 256) + 1] = tb[q];
                    }
                }
            }
            __syncthreads();

            // ---- MMA: 16 per-batch accumulators, k-pair packed ----
            ull acc[16];
#pragma unroll
            for (int b = 0; b < 16; b++) acc[b] = 0ULL;
#pragma unroll
            for (int i = 0; i < 8; i++) {
                const int off = i * 32 + ksub * 2;
#pragma unroll
                for (int b = 0; b < 16; b++) {
                    ulonglong2 q = *(const ulonglong2*)&tile0[b * 256 + off];
                    fma2(acc[b], wA[2 * i],     q.x);
                    fma2(acc[b], wA[2 * i + 1], q.y);
                }
            }
            if (isL1) {
#pragma unroll
                for (int i = 0; i < 8; i++) {
                    const int off = i * 32 + ksub * 2;
#pragma unroll
                    for (int b = 0; b < 16; b++) {
                        ulonglong2 q = *(const ulonglong2*)&tile1[b * 256 + off];
                        fma2(acc[b], wB[2 * i],     q.x);
                        fma2(acc[b], wB[2 * i + 1], q.y);
                    }
                }
            }

            // ---- fold even/odd-k halves, shfl over ksub parity, store partials ----
            float sv[16];
#pragma unroll
            for (int b = 0; b < 16; b++) {
                float2 p = unpack2(acc[b]);
                sv[b] = p.x + p.y;
            }
#pragma unroll
            for (int b = 0; b < 16; b++)
                sv[b] += __shfl_xor_sync(0xffffffffu, sv[b], 16);
            if ((tid & 31) < 16) {
#pragma unroll
                for (int b = 0; b < 16; b++)
                    red[wid * 256 + b * 16 + l] = sv[b];   // conflict-free
            }
            __syncthreads();

            // ---- gates: one (col, b) per thread ----
            {
                float sum = 0.f;
#pragma unroll
                for (int w = 0; w < 8; w++)
                    sum += red[w * 256 + gbG * 16 + gcolG];
                float v = sum + gxv + bh;
                gact[tid] = ((gcolG >> 2) == 2) ? tanh_f(v) : sigm_f(v);
            }
            __syncthreads();

            // ---- cell/hidden update: 32 threads, 2 units each ----
            if (tid < 32) {
                int jp = tid >> 4, b = tid & 15;
                float hx[2];
#pragma unroll
                for (int u = 0; u < 2; u++) {
                    int j = 2 * jp + u;
                    float iv = gact[(0  + j) * 16 + b];
                    float fv = gact[(4  + j) * 16 + b];
                    float gv = gact[(8  + j) * 16 + b];
                    float ov = gact[(12 + j) * 16 + b];
                    float c  = fv * cs[j * 16 + b] + iv * gv;
                    cs[j * 16 + b] = c;
                    hx[u] = ov * tanh_f(c);
                }
                if (isL1) {
                    dst1[b * 256 + (j0 >> 1) + jp] = pack2(hx[0], hx[1]);
                    if (s == TT) {
                        out[BB * HH + b * HH + j0 + 2 * jp]     = hx[0];
                        out[BB * HH + b * HH + j0 + 2 * jp + 1] = hx[1];
                    }
                } else {
                    dst0[b * 256 + (j0 >> 1) + jp] = pack2(hx[0], hx[1]);
                    if (s == TT - 1) {
                        out[b * HH + j0 + 2 * jp]     = hx[0];
                        out[b * HH + j0 + 2 * jp + 1] = hx[1];
                    }
                }
            }
        }
        grid_barrier(base + 2 + s);
    }
}

// =====================================================================
extern "C" void kernel_launch(void* const* d_in, const int* in_sizes, int n_in,
                              void* d_out, int out_size)
{
    const float* x      = (const float*)d_in[0];
    const float* h0     = (const float*)d_in[1];   // (2, B, H)
    const float* c0     = (const float*)d_in[2];   // (2, B, H)
    const float* w_ih_0 = (const float*)d_in[3];
    const float* w_hh_0 = (const float*)d_in[4];
    const float* b_ih_0 = (const float*)d_in[5];
    const float* b_hh_0 = (const float*)d_in[6];
    const float* w_ih_1 = (const float*)d_in[7];
    const float* w_hh_1 = (const float*)d_in[8];
    const float* b_ih_1 = (const float*)d_in[9];
    const float* b_hh_1 = (const float*)d_in[10];
    float* out = (float*)d_out;                    // (2, B, H)

    static int smem_set = 0;
    const int SMEMB = 75008;   // tiles 64K + red 8K + gact 1K + cs 256B
    if (!smem_set) {
        cudaFuncSetAttribute(lstm_dual,
                             cudaFuncAttributeMaxDynamicSharedMemorySize, SMEMB);
        smem_set = 1;
    }

    dim3 ggrid(16, 128);   // N/128, M/128
    gemm_xw<<<ggrid, 256>>>(x, w_ih_0, b_ih_0);
    lstm_dual<<<NBLK, NTHR, SMEMB>>>(w_hh_0, b_hh_0,
                                     w_ih_1, w_hh_1, b_ih_1, b_hh_1,
                                     h0, c0, out);
}

// round 10
// speedup vs baseline: 1.2704x; 1.0990x over previous
#include <cuda_runtime.h>

#define TT   1024
#define BB   16
#define HH   512
#define G4H  2048
#define NBLK 128
#define NTHR 512

typedef unsigned long long ull;

// ------------- device-global scratch (no runtime allocation allowed) -------------
__device__ float g_gx[(size_t)BB * TT * G4H];        // 134 MB: gx0[b][t][gatecol]
__device__ __align__(16) ull g_h0buf[2][16 * 256];   // h0 exchange, [b][kp] (h[b][2kp],h[b][2kp+1])
__device__ __align__(16) ull g_h1buf[2][16 * 256];   // h1 exchange
__device__ unsigned g_bar_count = 0;
__device__ unsigned g_bar_epoch = 0;

// ------------- packed f32x2 ops (only reachable via PTX) -------------
__device__ __forceinline__ void fma2(ull& d, ull a, ull b)
{
    asm("fma.rn.f32x2 %0, %1, %2, %0;" : "+l"(d) : "l"(a), "l"(b));
}
__device__ __forceinline__ ull pack2(float a, float b)
{
    ull r; asm("mov.b64 %0, {%1, %2};" : "=l"(r) : "f"(a), "f"(b)); return r;
}
__device__ __forceinline__ float2 unpack2(ull v)
{
    float2 r; asm("mov.b64 {%0, %1}, %2;" : "=f"(r.x), "=f"(r.y) : "l"(v)); return r;
}
__device__ __forceinline__ void ldcg_v2u64(ull& a, ull& b, const ull* p)
{
    asm volatile("ld.global.cg.v2.u64 {%0, %1}, [%2];" : "=l"(a), "=l"(b) : "l"(p));
}

// fast activations (MUFU-based, err ~1e-6)
__device__ __forceinline__ float sigm_f(float x) { return 1.f / (1.f + __expf(-x)); }
__device__ __forceinline__ float tanh_f(float x)
{
    float e = __expf(2.f * x);
    return 1.f - 2.f / (e + 1.f);
}

// =====================================================================
// GEMM (layer-0 input projection): g_gx[m][n] = sum_k X[m][k]*W[n][k] + bias[n]
// M=16384, N=2048, K=512. BM=BN=128, BK=16, 256 thr, 8x8 tiles, f32x2.
// =====================================================================
__global__ void __launch_bounds__(256, 2) gemm_xw(const float* __restrict__ X,
                                                  const float* __restrict__ W,
                                                  const float* __restrict__ bias)
{
    __shared__ float2 As[16][130];
    __shared__ float  Bs[16][132];

    const int m0  = blockIdx.y * 128;
    const int n0  = blockIdx.x * 128;
    const int tid = threadIdx.x;
    const int tm  = tid >> 4;
    const int tn  = tid & 15;
    const int lr  = tid >> 2;
    const int lk  = (tid & 3) * 4;

    ull acc[8][4];
#pragma unroll
    for (int i = 0; i < 8; i++)
#pragma unroll
        for (int j = 0; j < 4; j++) acc[i][j] = 0ULL;

    for (int k0 = 0; k0 < 512; k0 += 16) {
        float4 av0 = *(const float4*)&X[(size_t)(m0 + lr)      * 512 + k0 + lk];
        float4 av1 = *(const float4*)&X[(size_t)(m0 + lr + 64) * 512 + k0 + lk];
        float4 bv0 = *(const float4*)&W[(size_t)(n0 + lr)      * 512 + k0 + lk];
        float4 bv1 = *(const float4*)&W[(size_t)(n0 + lr + 64) * 512 + k0 + lk];

        __syncthreads();
        As[lk + 0][lr]      = make_float2(av0.x, av0.x);
        As[lk + 1][lr]      = make_float2(av0.y, av0.y);
        As[lk + 2][lr]      = make_float2(av0.z, av0.z);
        As[lk + 3][lr]      = make_float2(av0.w, av0.w);
        As[lk + 0][lr + 64] = make_float2(av1.x, av1.x);
        As[lk + 1][lr + 64] = make_float2(av1.y, av1.y);
        As[lk + 2][lr + 64] = make_float2(av1.z, av1.z);
        As[lk + 3][lr + 64] = make_float2(av1.w, av1.w);
        Bs[lk + 0][lr]      = bv0.x;
        Bs[lk + 1][lr]      = bv0.y;
        Bs[lk + 2][lr]      = bv0.z;
        Bs[lk + 3][lr]      = bv0.w;
        Bs[lk + 0][lr + 64] = bv1.x;
        Bs[lk + 1][lr + 64] = bv1.y;
        Bs[lk + 2][lr + 64] = bv1.z;
        Bs[lk + 3][lr + 64] = bv1.w;
        __syncthreads();

#pragma unroll
        for (int k = 0; k < 16; k++) {
            ull a[8], b[4];
            ulonglong2 q;
            q = *(const ulonglong2*)&As[k][tm * 8 + 0]; a[0] = q.x; a[1] = q.y;
            q = *(const ulonglong2*)&As[k][tm * 8 + 2]; a[2] = q.x; a[3] = q.y;
            q = *(const ulonglong2*)&As[k][tm * 8 + 4]; a[4] = q.x; a[5] = q.y;
            q = *(const ulonglong2*)&As[k][tm * 8 + 6]; a[6] = q.x; a[7] = q.y;
            q = *(const ulonglong2*)&Bs[k][tn * 8 + 0]; b[0] = q.x; b[1] = q.y;
            q = *(const ulonglong2*)&Bs[k][tn * 8 + 4]; b[2] = q.x; b[3] = q.y;
#pragma unroll
            for (int i = 0; i < 8; i++)
#pragma unroll
                for (int j = 0; j < 4; j++)
                    fma2(acc[i][j], a[i], b[j]);
        }
    }

    float bl[8];
#pragma unroll
    for (int j = 0; j < 8; j++) bl[j] = bias[n0 + tn * 8 + j];

#pragma unroll
    for (int i = 0; i < 8; i++) {
        int row = m0 + tm * 8 + i;
        float2 v0 = unpack2(acc[i][0]), v1 = unpack2(acc[i][1]);
        float2 v2 = unpack2(acc[i][2]), v3 = unpack2(acc[i][3]);
        float4 o0 = make_float4(v0.x + bl[0], v0.y + bl[1], v1.x + bl[2], v1.y + bl[3]);
        float4 o1 = make_float4(v2.x + bl[4], v2.y + bl[5], v3.x + bl[6], v3.y + bl[7]);
        *(float4*)&g_gx[(size_t)row * G4H + n0 + tn * 8]     = o0;
        *(float4*)&g_gx[(size_t)row * G4H + n0 + tn * 8 + 4] = o1;
    }
}

// =====================================================================
// Grid barrier for 128 co-resident blocks (1 per SM).
// =====================================================================
__device__ __forceinline__ void grid_barrier(unsigned target)
{
    __threadfence();
    __syncthreads();
    if (threadIdx.x == 0) {
        unsigned t = atomicAdd(&g_bar_count, 1);
        if (t == NBLK - 1) {
            atomicExch(&g_bar_count, 0);
            __threadfence();
            atomicAdd(&g_bar_epoch, 1);
        } else {
            while ((int)(*(volatile unsigned*)&g_bar_epoch - target) < 0) { }
        }
    }
    __syncthreads();
}

// =====================================================================
// Both-layer persistent LSTM. 128 identical blocks x 512 threads, 1/SM.
// Block owns units j0..j0+3 of BOTH layers. Super-step s: h0(s), h1(s-1).
// Warps 0-7 (role 0): w_hh0 @ h0(s-1).
// Warps 8-15 (role 1): w_ih1 @ h0(s-1) + w_hh1 @ h1(s-2), ONE accumulator.
// MMA thread (l = rt&15, ksub = rt>>4): k-pair-packed weights in regs
// (16 ull per matrix), 16 per-batch ull accs (f32x2 = k-parity lanes).
// h loads: ulonglong2, 2 adjacent 16B chunks/warp, 16-way bcast, no conflicts.
// Reduce: fold parity + shfl_xor(16) + padded smem tree (conflict-free).
// =====================================================================
__global__ void __launch_bounds__(NTHR, 1) lstm_both(
    const float* __restrict__ w_hh0, const float* __restrict__ b_hh0,
    const float* __restrict__ w_ih1, const float* __restrict__ w_hh1,
    const float* __restrict__ b_ih1, const float* __restrict__ b_hh1,
    const float* __restrict__ h0in,  const float* __restrict__ c0in,
    float* __restrict__ out)
{
    extern __shared__ __align__(16) char smraw[];
    ull*   tile0 = (ull*)(smraw);            // h0(s-1) [b][kp], 32 KB
    ull*   tile1 = (ull*)(smraw + 32768);    // h1(s-2) [b][kp], 32 KB
    float* red   = (float*)(smraw + 65536);  // [w][b*17+l] padded, 17408 B
    float* gact0 = (float*)(smraw + 82944);  // [col*17+b], 1088 B
    float* gact1 = (float*)(smraw + 84032);  // 1088 B
    float* cs0   = (float*)(smraw + 85120);  // [j][b], 256 B
    float* cs1   = (float*)(smraw + 85376);  // 256 B

    const int tid  = threadIdx.x;
    const int blk  = blockIdx.x;
    const int j0   = blk * 4;
    const int role = tid >> 8;           // 0: layer0 MMA, 1: layer1 MMA
    const int rt   = tid & 255;
    const int l    = rt & 15;
    const int ksub = rt >> 4;
    const int wid  = tid >> 5;           // 0..15
    const int gcol = (l >> 2) * 512 + j0 + (l & 3);

    // ---- weights into registers, k-pair packed ----
    ull wP[16], wQ[16];
    {
        const float* srcP = role ? w_ih1 : w_hh0;
#pragma unroll
        for (int i = 0; i < 8; i++) {
            float4 w4 = *(const float4*)&srcP[(size_t)gcol * 512 + i * 64 + ksub * 4];
            wP[2 * i]     = pack2(w4.x, w4.y);
            wP[2 * i + 1] = pack2(w4.z, w4.w);
        }
        if (role) {
#pragma unroll
            for (int i = 0; i < 8; i++) {
                float4 w4 = *(const float4*)&w_hh1[(size_t)gcol * 512 + i * 64 + ksub * 4];
                wQ[2 * i]     = pack2(w4.x, w4.y);
                wQ[2 * i + 1] = pack2(w4.z, w4.w);
            }
        } else {
#pragma unroll
            for (int i = 0; i < 16; i++) wQ[i] = 0ULL;
        }
    }

    // ---- gates-role constants ----
    // gates0: tid 0..255 -> (gc0 = tid&15 col, gb0 = tid>>4 batch)
    const int gc0 = tid & 15;
    const int gb0 = (tid >> 4) & 15;
    const int gg0 = (gc0 >> 2) * 512 + j0 + (gc0 & 3);
    float bh0v = 0.f;
    if (tid < 256) bh0v = b_hh0[gg0];
    // gates1: tid 256..511 -> (gc1, gb1)
    const int gc1 = rt & 15;
    const int gb1 = (rt >> 4) & 15;
    const int gg1 = (gc1 >> 2) * 512 + j0 + (gc1 & 3);
    float bh1v = 0.f;
    if (tid >= 256) bh1v = b_ih1[gg1] + b_hh1[gg1];

    // ---- init cell states + initial h exchange ----
    if (tid < 64) {
        int j = tid >> 4, b = tid & 15;
        cs0[j * 16 + b] = c0in[b * 512 + j0 + j];
    } else if (tid < 128) {
        int j = (tid - 64) >> 4, b = tid & 15;
        cs1[j * 16 + b] = c0in[BB * HH + b * 512 + j0 + j];
    }
    if (tid < 32) {
        int jp = tid >> 4, b = tid & 15;
        g_h0buf[1][b * 256 + (j0 >> 1) + jp] =
            pack2(h0in[b * 512 + j0 + 2 * jp], h0in[b * 512 + j0 + 2 * jp + 1]);
    } else if (tid < 64) {
        int jp = (tid - 32) >> 4, b = tid & 15;
        g_h1buf[1][b * 256 + (j0 >> 1) + jp] =
            pack2(h0in[BB * HH + b * 512 + j0 + 2 * jp],
                  h0in[BB * HH + b * 512 + j0 + 2 * jp + 1]);
    }

    unsigned base = 0;
    if (tid == 0) base = *(volatile unsigned*)&g_bar_epoch;
    grid_barrier(base + 1);

    for (int s = 0; s <= TT; s++) {
        const ull* src0 = g_h0buf[(s + 1) & 1];   // h0(s-1)
        ull*       dst0 = g_h0buf[s & 1];         // h0(s)
        const ull* src1 = g_h1buf[s & 1];         // h1(s-2)
        ull*       dst1 = g_h1buf[(s + 1) & 1];   // h1(s-1)

        // gx prefetch for gates0 (DRAM; consumed ~2000 cyc later)
        float gxv = 0.f;
        if (tid < 256 && s < TT)
            gxv = g_gx[((size_t)gb0 * TT + s) * G4H + gg0];

        // ---- stage both h tiles (L1 bypass), 4 x 16B per thread per tile ----
        {
            ull ta[4], tb[4];
#pragma unroll
            for (int q = 0; q < 4; q++)
                ldcg_v2u64(ta[q], tb[q], src0 + 2 * (tid + q * 512));
#pragma unroll
            for (int q = 0; q < 4; q++)
                *(ulonglong2*)&tile0[2 * (tid + q * 512)] = make_ulonglong2(ta[q], tb[q]);
#pragma unroll
            for (int q = 0; q < 4; q++)
                ldcg_v2u64(ta[q], tb[q], src1 + 2 * (tid + q * 512));
#pragma unroll
            for (int q = 0; q < 4; q++)
                *(ulonglong2*)&tile1[2 * (tid + q * 512)] = make_ulonglong2(ta[q], tb[q]);
        }
        __syncthreads();

        // ---- MMA: 16 per-batch accs; role1 folds both its matrices in ----
        ull acc[16];
#pragma unroll
        for (int b = 0; b < 16; b++) acc[b] = 0ULL;
#pragma unroll
        for (int i = 0; i < 8; i++) {
            const int off = i * 32 + ksub * 2;
#pragma unroll
            for (int b = 0; b < 16; b++) {
                ulonglong2 q = *(const ulonglong2*)&tile0[b * 256 + off];
                fma2(acc[b], wP[2 * i],     q.x);
                fma2(acc[b], wP[2 * i + 1], q.y);
            }
        }
        if (role) {
#pragma unroll
            for (int i = 0; i < 8; i++) {
                const int off = i * 32 + ksub * 2;
#pragma unroll
                for (int b = 0; b < 16; b++) {
                    ulonglong2 q = *(const ulonglong2*)&tile1[b * 256 + off];
                    fma2(acc[b], wQ[2 * i],     q.x);
                    fma2(acc[b], wQ[2 * i + 1], q.y);
                }
            }
        }

        // ---- fold k-parity, shfl over ksub LSB, padded smem partials ----
        {
            float sv[16];
#pragma unroll
            for (int b = 0; b < 16; b++) {
                float2 p = unpack2(acc[b]);
                sv[b] = p.x + p.y;
            }
#pragma unroll
            for (int b = 0; b < 16; b++)
                sv[b] += __shfl_xor_sync(0xffffffffu, sv[b], 16);
            if ((tid & 31) < 16) {
#pragma unroll
                for (int b = 0; b < 16; b++)
                    red[wid * 272 + b * 17 + l] = sv[b];   // conflict-free
            }
        }
        __syncthreads();

        // ---- gates (padded reads, conflict-free) ----
        if (tid < 256) {
            float sum = 0.f;
#pragma unroll
            for (int w = 0; w < 8; w++)
                sum += red[w * 272 + gb0 * 17 + gc0];
            float v = sum + gxv + bh0v;
            gact0[gc0 * 17 + gb0] = ((gc0 >> 2) == 2) ? tanh_f(v) : sigm_f(v);
        } else {
            float sum = 0.f;
#pragma unroll
            for (int w = 8; w < 16; w++)
                sum += red[w * 272 + gb1 * 17 + gc1];
            float v = sum + bh1v;
            gact1[gc1 * 17 + gb1] = ((gc1 >> 2) == 2) ? tanh_f(v) : sigm_f(v);
        }
        __syncthreads();

        // ---- cell/hidden updates ----
        if (tid < 32) {                       // layer 0, valid for s < TT
            if (s < TT) {
                int jp = tid >> 4, b = tid & 15;
                float hx[2];
#pragma unroll
                for (int u = 0; u < 2; u++) {
                    int j = 2 * jp + u;
                    float iv = gact0[(0  + j) * 17 + b];
                    float fv = gact0[(4  + j) * 17 + b];
                    float gv = gact0[(8  + j) * 17 + b];
                    float ov = gact0[(12 + j) * 17 + b];
                    float c  = fv * cs0[j * 16 + b] + iv * gv;
                    cs0[j * 16 + b] = c;
                    hx[u] = ov * tanh_f(c);
                }
                dst0[(tid & 15) * 256 + (j0 >> 1) + (tid >> 4)] = pack2(hx[0], hx[1]);
                if (s == TT - 1) {
                    int b = tid & 15, jp = tid >> 4;
                    out[b * HH + j0 + 2 * jp]     = hx[0];
                    out[b * HH + j0 + 2 * jp + 1] = hx[1];
                }
            }
        } else if (tid < 64) {                // layer 1, valid for s >= 1
            if (s >= 1) {
                int jp = (tid - 32) >> 4, b = tid & 15;
                float hx[2];
#pragma unroll
                for (int u = 0; u < 2; u++) {
                    int j = 2 * jp + u;
                    float iv = gact1[(0  + j) * 17 + b];
                    float fv = gact1[(4  + j) * 17 + b];
                    float gv = gact1[(8  + j) * 17 + b];
                    float ov = gact1[(12 + j) * 17 + b];
                    float c  = fv * cs1[j * 16 + b] + iv * gv;
                    cs1[j * 16 + b] = c;
                    hx[u] = ov * tanh_f(c);
                }
                dst1[b * 256 + (j0 >> 1) + jp] = pack2(hx[0], hx[1]);
                if (s == TT) {
                    out[BB * HH + b * HH + j0 + 2 * jp]     = hx[0];
                    out[BB * HH + b * HH + j0 + 2 * jp + 1] = hx[1];
                }
            }
        }
        grid_barrier(base + 2 + s);
    }
}

// =====================================================================
extern "C" void kernel_launch(void* const* d_in, const int* in_sizes, int n_in,
                              void* d_out, int out_size)
{
    const float* x      = (const float*)d_in[0];
    const float* h0     = (const float*)d_in[1];   // (2, B, H)
    const float* c0     = (const float*)d_in[2];   // (2, B, H)
    const float* w_ih_0 = (const float*)d_in[3];
    const float* w_hh_0 = (const float*)d_in[4];
    const float* b_ih_0 = (const float*)d_in[5];
    const float* b_hh_0 = (const float*)d_in[6];
    const float* w_ih_1 = (const float*)d_in[7];
    const float* w_hh_1 = (const float*)d_in[8];
    const float* b_ih_1 = (const float*)d_in[9];
    const float* b_hh_1 = (const float*)d_in[10];
    float* out = (float*)d_out;                    // (2, B, H)

    static int smem_set = 0;
    const int SMEMB = 85632;
    if (!smem_set) {
        cudaFuncSetAttribute(lstm_both,
                             cudaFuncAttributeMaxDynamicSharedMemorySize, SMEMB);
        smem_set = 1;
    }

    dim3 ggrid(16, 128);   // N/128, M/128
    gemm_xw<<<ggrid, 256>>>(x, w_ih_0, b_ih_0);
    lstm_both<<<NBLK, NTHR, SMEMB>>>(w_hh_0, b_hh_0,
                                     w_ih_1, w_hh_1, b_ih_1, b_hh_1,
                                     h0, c0, out);
}